// round 3
// baseline (speedup 1.0000x reference)
#include <cuda_runtime.h>
#include <math.h>
#include <stdint.h>

#define NN 50000
#define EE 800000
#define HD 128
#define GG 64

// ---------------- scratch (device globals: allocation-free) ----------------
__device__ float g_z[NN * HD];
__device__ float g_h[NN * HD];
__device__ float g_dinv[NN];
__device__ int   g_degi[NN];
__device__ int   g_rowptr[NN + 1];
__device__ int   g_cursor[NN];
__device__ int   g_col[EE];
__device__ int   g_bsum[64];
__device__ float g_f[GG * HD];
__device__ float g_t1[GG * 1024];
__device__ float g_t2[GG * 512];
__device__ float g_t3[GG * 256];
__device__ float g_t4[GG * HD];
__device__ float g_wTh[3 * HD * HD];   // W^T hi (tf32-exact), per layer
__device__ float g_wTl[3 * HD * HD];   // W^T lo (tf32 of residual)

// ---------------- helpers ----------------
__device__ __forceinline__ float tf32_trunc(float x) {
    return __uint_as_float(__float_as_uint(x) & 0xFFFFE000u);
}
__device__ __forceinline__ float tf32_rna(float x) {
    uint32_t r; asm("cvt.rna.tf32.f32 %0, %1;" : "=r"(r) : "f"(x));
    return __uint_as_float(r);
}
__device__ __forceinline__ void mma_tf32(float* c, const uint32_t* a, const uint32_t* b) {
    asm volatile(
        "mma.sync.aligned.m16n8k8.row.col.f32.tf32.tf32.f32 "
        "{%0,%1,%2,%3}, {%4,%5,%6,%7}, {%8,%9}, {%0,%1,%2,%3};"
        : "+f"(c[0]), "+f"(c[1]), "+f"(c[2]), "+f"(c[3])
        : "r"(a[0]), "r"(a[1]), "r"(a[2]), "r"(a[3]), "r"(b[0]), "r"(b[1]));
}

// ---------------- CSR build ----------------
__global__ void k_count(const int* __restrict__ ei) {
    int e = blockIdx.x * blockDim.x + threadIdx.x;
    if (e < EE) atomicAdd(&g_degi[ei[EE + e]], 1);
}
__global__ void k_scan1() {
    __shared__ int s[1024];
    int t = threadIdx.x;
    int i = blockIdx.x * 1024 + t;
    int v = (i < NN) ? g_degi[i] : 0;
    s[t] = v;
    __syncthreads();
    for (int off = 1; off < 1024; off <<= 1) {
        int x = (t >= off) ? s[t - off] : 0;
        __syncthreads();
        s[t] += x;
        __syncthreads();
    }
    if (i < NN) g_rowptr[i] = s[t] - v;
    if (t == 1023) g_bsum[blockIdx.x] = s[1023];
}
__global__ void k_scan2(int nb) {
    __shared__ int s[64];
    int t = threadIdx.x;
    int v = (t < nb) ? g_bsum[t] : 0;
    s[t] = v;
    __syncthreads();
    for (int off = 1; off < 64; off <<= 1) {
        int x = (t >= off) ? s[t - off] : 0;
        __syncthreads();
        s[t] += x;
        __syncthreads();
    }
    if (t < nb) g_bsum[t] = s[t] - v;
}
__global__ void k_scan3() {
    int i = blockIdx.x * 1024 + threadIdx.x;
    if (i < NN) {
        int rp = g_rowptr[i] + g_bsum[blockIdx.x];
        g_rowptr[i] = rp;
        g_cursor[i] = rp;
        g_dinv[i]   = rsqrtf((float)(g_degi[i] + 1));
    }
    if (i == 0) g_rowptr[NN] = EE;
}
__global__ void k_fill(const int* __restrict__ ei) {
    int e = blockIdx.x * blockDim.x + threadIdx.x;
    if (e < EE) {
        int src = ei[e];
        int dst = ei[EE + e];
        int p = atomicAdd(&g_cursor[dst], 1);
        g_col[p] = src;
    }
}

// ---------------- weight prep: W[k][n] -> WT[n][k] hi/lo split --------------
__global__ __launch_bounds__(256) void k_prep(const float* __restrict__ w1,
                                              const float* __restrict__ w2,
                                              const float* __restrict__ w3) {
    const float* W = (blockIdx.x == 0) ? w1 : ((blockIdx.x == 1) ? w2 : w3);
    float* oh = g_wTh + blockIdx.x * (HD * HD);
    float* ol = g_wTl + blockIdx.x * (HD * HD);
    for (int idx = threadIdx.x; idx < HD * HD; idx += 256) {
        int k = idx >> 7;
        int n = idx & 127;
        float w = W[idx];
        float hi = tf32_trunc(w);
        float lo = tf32_rna(w - hi);
        oh[n * HD + k] = hi;
        ol[n * HD + k] = lo;
    }
}

// ---------------- tf32 mma.sync GEMM (3xTF32): C = dinv[r]*(A @ W) ---------
// A: [M,128] fp32. WT hi/lo: [128n][128k]. C: [M,128].
// Block: 128x128, 8 warps (4 m x 2 n), warp tile 32x64. BK=32, 4 chunks.
#define APITCH 36
#define SM_ASH 0
#define SM_ASL (128 * APITCH)
#define SM_BSH (2 * 128 * APITCH)
#define SM_BSL (3 * 128 * APITCH)
#define SM_GEMM_FLOATS (4 * 128 * APITCH)

__global__ __launch_bounds__(256, 2) void k_gemm_tc(const float* __restrict__ A,
                                                    const float* __restrict__ WTh,
                                                    const float* __restrict__ WTl,
                                                    float* __restrict__ C,
                                                    int M) {
    extern __shared__ float sm[];
    int tid  = threadIdx.x;
    int wid  = tid >> 5;
    int lane = tid & 31;
    int g    = lane >> 2;     // groupID
    int tig  = lane & 3;      // thread in group
    int wm   = wid & 3;       // warp m index (0..3)
    int wn   = wid >> 2;      // warp n index (0..1)
    int base = blockIdx.x * 128;

    float c[2][8][4];
    #pragma unroll
    for (int f = 0; f < 2; f++)
        #pragma unroll
        for (int j = 0; j < 8; j++)
            #pragma unroll
            for (int q = 0; q < 4; q++) c[f][j][q] = 0.f;

    for (int kc = 0; kc < 4; kc++) {
        int k0 = kc * 32;
        // --- stage A chunk [128 x 32] with hi/lo split ---
        #pragma unroll
        for (int i = 0; i < 4; i++) {
            int idx = i * 256 + tid;           // 0..1023 float4s
            int row = idx >> 3;
            int c4  = (idx & 7) * 4;
            float4 a = make_float4(0.f, 0.f, 0.f, 0.f);
            int gr = base + row;
            if (gr < M) a = *(const float4*)(A + (size_t)gr * HD + k0 + c4);
            float4 ah, al;
            ah.x = tf32_trunc(a.x); al.x = tf32_rna(a.x - ah.x);
            ah.y = tf32_trunc(a.y); al.y = tf32_rna(a.y - ah.y);
            ah.z = tf32_trunc(a.z); al.z = tf32_rna(a.z - ah.z);
            ah.w = tf32_trunc(a.w); al.w = tf32_rna(a.w - ah.w);
            *(float4*)(sm + SM_ASH + row * APITCH + c4) = ah;
            *(float4*)(sm + SM_ASL + row * APITCH + c4) = al;
        }
        // --- stage B chunk: WT[n][k0..k0+31], already split ---
        #pragma unroll
        for (int i = 0; i < 4; i++) {
            int idx = i * 256 + tid;
            int n  = idx >> 3;
            int c4 = (idx & 7) * 4;
            *(float4*)(sm + SM_BSH + n * APITCH + c4) = *(const float4*)(WTh + (size_t)n * HD + k0 + c4);
            *(float4*)(sm + SM_BSL + n * APITCH + c4) = *(const float4*)(WTl + (size_t)n * HD + k0 + c4);
        }
        __syncthreads();

        #pragma unroll
        for (int ks = 0; ks < 4; ks++) {
            int k = ks * 8;
            uint32_t ah[2][4], al[2][4];
            #pragma unroll
            for (int f = 0; f < 2; f++) {
                int r0 = (wm * 32 + f * 16 + g) * APITCH + k + tig;
                int r1 = (wm * 32 + f * 16 + 8 + g) * APITCH + k + tig;
                ah[f][0] = __float_as_uint(sm[SM_ASH + r0]);
                ah[f][1] = __float_as_uint(sm[SM_ASH + r1]);
                ah[f][2] = __float_as_uint(sm[SM_ASH + r0 + 4]);
                ah[f][3] = __float_as_uint(sm[SM_ASH + r1 + 4]);
                al[f][0] = __float_as_uint(sm[SM_ASL + r0]);
                al[f][1] = __float_as_uint(sm[SM_ASL + r1]);
                al[f][2] = __float_as_uint(sm[SM_ASL + r0 + 4]);
                al[f][3] = __float_as_uint(sm[SM_ASL + r1 + 4]);
            }
            #pragma unroll
            for (int j = 0; j < 8; j++) {
                int nb = (wn * 64 + j * 8 + g) * APITCH + k + tig;
                uint32_t bh[2], bl[2];
                bh[0] = __float_as_uint(sm[SM_BSH + nb]);
                bh[1] = __float_as_uint(sm[SM_BSH + nb + 4]);
                bl[0] = __float_as_uint(sm[SM_BSL + nb]);
                bl[1] = __float_as_uint(sm[SM_BSL + nb + 4]);
                #pragma unroll
                for (int f = 0; f < 2; f++) {
                    mma_tf32(c[f][j], ah[f], bh);
                    mma_tf32(c[f][j], ah[f], bl);
                    mma_tf32(c[f][j], al[f], bh);
                }
            }
        }
        __syncthreads();
    }

    // epilogue: scale by dinv[row], store float2 pairs
    #pragma unroll
    for (int f = 0; f < 2; f++) {
        int r0 = base + wm * 32 + f * 16 + g;
        int r1 = r0 + 8;
        float d0 = (r0 < M) ? g_dinv[r0] : 0.f;
        float d1 = (r1 < M) ? g_dinv[r1] : 0.f;
        #pragma unroll
        for (int j = 0; j < 8; j++) {
            int col = wn * 64 + j * 8 + 2 * tig;
            if (r0 < M) {
                float2 o0 = make_float2(c[f][j][0] * d0, c[f][j][1] * d0);
                *(float2*)(C + (size_t)r0 * HD + col) = o0;
            }
            if (r1 < M) {
                float2 o1 = make_float2(c[f][j][2] * d1, c[f][j][3] * d1);
                *(float2*)(C + (size_t)r1 * HD + col) = o1;
            }
        }
    }
}

// ---------------- aggregation: one warp per node ----------------
__global__ __launch_bounds__(256) void k_agg(const float* __restrict__ z,
                                             const float* __restrict__ bias,
                                             float* __restrict__ out,
                                             int relu) {
    int wid  = (blockIdx.x * blockDim.x + threadIdx.x) >> 5;
    int lane = threadIdx.x & 31;
    if (wid >= NN) return;
    const float4* z4 = (const float4*)z;
    float4 acc = z4[(size_t)wid * 32 + lane];
    int beg = g_rowptr[wid];
    int end = g_rowptr[wid + 1];
    int j = beg;
    for (; j + 3 < end; j += 4) {
        int u0 = g_col[j], u1 = g_col[j + 1], u2 = g_col[j + 2], u3 = g_col[j + 3];
        float4 a = z4[(size_t)u0 * 32 + lane];
        float4 b = z4[(size_t)u1 * 32 + lane];
        float4 c = z4[(size_t)u2 * 32 + lane];
        float4 d = z4[(size_t)u3 * 32 + lane];
        acc.x += (a.x + b.x) + (c.x + d.x);
        acc.y += (a.y + b.y) + (c.y + d.y);
        acc.z += (a.z + b.z) + (c.z + d.z);
        acc.w += (a.w + b.w) + (c.w + d.w);
    }
    for (; j < end; j++) {
        float4 a = z4[(size_t)g_col[j] * 32 + lane];
        acc.x += a.x; acc.y += a.y; acc.z += a.z; acc.w += a.w;
    }
    float dv = g_dinv[wid];
    float4 bb = ((const float4*)bias)[lane];
    float4 r;
    r.x = fmaf(acc.x, dv, bb.x);
    r.y = fmaf(acc.y, dv, bb.y);
    r.z = fmaf(acc.z, dv, bb.z);
    r.w = fmaf(acc.w, dv, bb.w);
    if (relu) {
        r.x = fmaxf(r.x, 0.f); r.y = fmaxf(r.y, 0.f);
        r.z = fmaxf(r.z, 0.f); r.w = fmaxf(r.w, 0.f);
    }
    ((float4*)out)[(size_t)wid * 32 + lane] = r;
}

// ---------------- mean pool per graph ----------------
__global__ __launch_bounds__(128) void k_pool(const float* __restrict__ h,
                                              const int* __restrict__ batch,
                                              float* __restrict__ dout) {
    int g = blockIdx.x;
    int c = threadIdx.x;
    int lo = 0, hi = NN;
    while (lo < hi) { int m = (lo + hi) >> 1; if (batch[m] < g) lo = m + 1; else hi = m; }
    int start = lo;
    lo = 0; hi = NN;
    while (lo < hi) { int m = (lo + hi) >> 1; if (batch[m] < g + 1) lo = m + 1; else hi = m; }
    int end = lo;
    float s = 0.f;
    for (int v = start; v < end; v++) s += h[(size_t)v * 128 + c];
    float cnt = (float)(end - start);
    float val = s / fmaxf(cnt, 1.0f);
    g_f[g * 128 + c] = val;
    dout[g * 128 + c] = val;
}

// ---------------- MLP layer: 64 graphs x 32-col slice per block ------------
__global__ __launch_bounds__(256) void k_fc(const float* __restrict__ in,
                                            const float* __restrict__ W,
                                            const float* __restrict__ b,
                                            float* __restrict__ out,
                                            int K, int C, int relu) {
    __shared__ float s_in[64 * 64];
    int tx = threadIdx.x & 31;
    int ty = threadIdx.x >> 5;
    int c  = blockIdx.x * 32 + tx;
    int ce = (c < C) ? c : (C - 1);
    float acc[8];
    #pragma unroll
    for (int j = 0; j < 8; j++) acc[j] = 0.f;
    for (int k0 = 0; k0 < K; k0 += 64) {
        #pragma unroll
        for (int i = 0; i < 16; i++) {
            int idx = i * 256 + threadIdx.x;
            int g = idx >> 6, k = idx & 63;
            s_in[idx] = in[(size_t)g * K + k0 + k];
        }
        __syncthreads();
        #pragma unroll 4
        for (int k = 0; k < 64; k++) {
            float w = W[(size_t)(k0 + k) * C + ce];
            #pragma unroll
            for (int j = 0; j < 8; j++)
                acc[j] = fmaf(s_in[(ty * 8 + j) * 64 + k], w, acc[j]);
        }
        __syncthreads();
    }
    if (c < C) {
        float bias = b[c];
        #pragma unroll
        for (int j = 0; j < 8; j++) {
            float v = acc[j] + bias;
            if (relu) v = fmaxf(v, 0.f);
            out[(size_t)(ty * 8 + j) * C + c] = v;
        }
    }
}

extern "C" void kernel_launch(void* const* d_in, const int* in_sizes, int n_in,
                              void* d_out, int out_size) {
    const float* x     = (const float*)d_in[0];
    const int*   ei    = (const int*)d_in[1];
    const int*   batch = (const int*)d_in[2];
    const float* c1w = (const float*)d_in[3];
    const float* c1b = (const float*)d_in[4];
    const float* c2w = (const float*)d_in[5];
    const float* c2b = (const float*)d_in[6];
    const float* c3w = (const float*)d_in[7];
    const float* c3b = (const float*)d_in[8];
    const float* f1w = (const float*)d_in[9];
    const float* f1b = (const float*)d_in[10];
    const float* f2w = (const float*)d_in[11];
    const float* f2b = (const float*)d_in[12];
    const float* f3w = (const float*)d_in[13];
    const float* f3b = (const float*)d_in[14];
    const float* f4w = (const float*)d_in[15];
    const float* f4b = (const float*)d_in[16];
    const float* f5w = (const float*)d_in[17];
    const float* f5b = (const float*)d_in[18];
    float* dout = (float*)d_out;

    float *p_z, *p_h, *p_f, *p_t1, *p_t2, *p_t3, *p_t4, *p_wTh, *p_wTl;
    int* p_degi;
    cudaGetSymbolAddress((void**)&p_z,   g_z);
    cudaGetSymbolAddress((void**)&p_h,   g_h);
    cudaGetSymbolAddress((void**)&p_f,   g_f);
    cudaGetSymbolAddress((void**)&p_t1,  g_t1);
    cudaGetSymbolAddress((void**)&p_t2,  g_t2);
    cudaGetSymbolAddress((void**)&p_t3,  g_t3);
    cudaGetSymbolAddress((void**)&p_t4,  g_t4);
    cudaGetSymbolAddress((void**)&p_wTh, g_wTh);
    cudaGetSymbolAddress((void**)&p_wTl, g_wTl);
    cudaGetSymbolAddress((void**)&p_degi, g_degi);

    static int smem_set = 0;
    if (!smem_set) {
        cudaFuncSetAttribute(k_gemm_tc, cudaFuncAttributeMaxDynamicSharedMemorySize,
                             SM_GEMM_FLOATS * sizeof(float));
        smem_set = 1;
    }

    int nb = (NN + 1023) / 1024;

    // CSR + normalization build (+ weight prep, independent)
    cudaMemsetAsync(p_degi, 0, NN * sizeof(int));
    k_prep<<<3, 256>>>(c1w, c2w, c3w);
    k_count<<<(EE + 255) / 256, 256>>>(ei);
    k_scan1<<<nb, 1024>>>();
    k_scan2<<<1, 64>>>(nb);
    k_scan3<<<nb, 1024>>>();
    k_fill<<<(EE + 255) / 256, 256>>>(ei);

    int gemm_blocks = (NN + 127) / 128;
    int agg_blocks  = (NN * 32 + 255) / 256;
    size_t gsm = SM_GEMM_FLOATS * sizeof(float);

    k_gemm_tc<<<gemm_blocks, 256, gsm>>>(x, p_wTh, p_wTl, p_z, NN);
    k_agg<<<agg_blocks, 256>>>(p_z, c1b, p_h, 1);
    k_gemm_tc<<<gemm_blocks, 256, gsm>>>(p_h, p_wTh + HD * HD, p_wTl + HD * HD, p_z, NN);
    k_agg<<<agg_blocks, 256>>>(p_z, c2b, p_h, 1);
    k_gemm_tc<<<gemm_blocks, 256, gsm>>>(p_h, p_wTh + 2 * HD * HD, p_wTl + 2 * HD * HD, p_z, NN);
    k_agg<<<agg_blocks, 256>>>(p_z, c3b, p_h, 0);

    k_pool<<<GG, 128>>>(p_h, batch, dout);

    k_fc<<<32, 256>>>(p_f,  f1w, f1b, p_t1, 128,  1024, 1);
    k_fc<<<16, 256>>>(p_t1, f2w, f2b, p_t2, 1024, 512,  1);
    k_fc<<<8,  256>>>(p_t2, f3w, f3b, p_t3, 512,  256,  1);
    k_fc<<<4,  256>>>(p_t3, f4w, f4b, p_t4, 256,  128,  1);
    k_fc<<<1,  256>>>(p_t4, f5w, f5b, dout + GG * HD, 128, 10, 0);
}